// round 1
// baseline (speedup 1.0000x reference)
#include <cuda_runtime.h>
#include <math.h>

#define NNODES 50000
#define MPAD   50048      // 391 * 128, padded rows for unguarded GEMM stores
#define KD     256
#define HEADS  4
#define EMAX   1700000

// ---------------- scratch (device globals: sanctioned scratch mechanism) ----
__device__ float    g_hs[MPAD * KD];        // source transform (per layer)
__device__ float    g_buf[MPAD * KD];       // layer activations
__device__ float    g_as[NNODES * HEADS];
__device__ float    g_ad[NNODES * HEADS];
__device__ float    g_vd[KD * HEADS];       // Wd @ att_d (per head)
__device__ unsigned g_amax[NNODES * HEADS];
__device__ float    g_denom[NNODES * HEADS];
__device__ float4   g_w[EMAX];              // per-edge alpha -> exp values (4 heads)
__device__ int      g_deg[NNODES];
__device__ int      g_rowptr[NNODES + 1];
__device__ int      g_cursor[NNODES];
__device__ int      g_eids[EMAX];

// ---------------- helpers ---------------------------------------------------
__device__ __forceinline__ unsigned encf(float f) {
    unsigned u = __float_as_uint(f);
    return (u & 0x80000000u) ? ~u : (u | 0x80000000u);
}
__device__ __forceinline__ float decf(unsigned u) {
    return __uint_as_float((u & 0x80000000u) ? (u ^ 0x80000000u) : ~u);
}

// ---------------- CSR build -------------------------------------------------
__global__ void clear_deg_kernel() {
    int i = blockIdx.x * blockDim.x + threadIdx.x;
    if (i < NNODES) g_deg[i] = 0;
}

__global__ void count_deg_kernel(const int* __restrict__ dst, int e2) {
    int e = blockIdx.x * blockDim.x + threadIdx.x;
    if (e < e2) atomicAdd(&g_deg[dst[e]], 1);
}

__global__ void scan_kernel() {
    __shared__ int s[1024];
    int t = threadIdx.x;
    const int per = (NNODES + 1023) / 1024;   // 49
    int start = t * per;
    int end = start + per; if (end > NNODES) end = NNODES;
    int sum = 0;
    for (int i = start; i < end && i < NNODES; i++) sum += g_deg[i];
    s[t] = sum;
    __syncthreads();
    // Hillis-Steele inclusive scan
    for (int off = 1; off < 1024; off <<= 1) {
        int v = (t >= off) ? s[t - off] : 0;
        __syncthreads();
        s[t] += v;
        __syncthreads();
    }
    int run = (t > 0) ? s[t - 1] : 0;
    for (int i = start; i < end && i < NNODES; i++) {
        int d = g_deg[i];
        g_rowptr[i] = run;
        g_cursor[i] = run;
        run += d;
    }
    if (t == 0) g_rowptr[NNODES] = s[1023];
}

__global__ void scatter_kernel(const int* __restrict__ dst, int e2) {
    int e = blockIdx.x * blockDim.x + threadIdx.x;
    if (e < e2) {
        int pos = atomicAdd(&g_cursor[dst[e]], 1);
        g_eids[pos] = e;
    }
}

// ---------------- GEMM: C(g_hs)[MPAD,256] = A[M,256] @ B[256,256] -----------
// BM=128, BN=128, BK=8, 256 threads, 8x8 microtile.
__global__ void __launch_bounds__(256) gemm_kernel(const float* __restrict__ A,
                                                   const float* __restrict__ B,
                                                   int M) {
    __shared__ float As[8][128];
    __shared__ float Bs[8][128];
    const int tid = threadIdx.x;
    const int tx = tid & 15;        // col group
    const int ty = tid >> 4;        // row group
    const int row0 = blockIdx.x * 128;
    const int col0 = blockIdx.y * 128;

    const int aRow = tid >> 1;          // 0..127
    const int aCol = (tid & 1) * 4;     // 0 or 4
    const int bRow = tid >> 5;          // 0..7
    const int bCol = (tid & 31) * 4;    // 0..124

    float acc[8][8];
#pragma unroll
    for (int i = 0; i < 8; i++)
#pragma unroll
        for (int j = 0; j < 8; j++) acc[i][j] = 0.f;

    for (int k0 = 0; k0 < KD; k0 += 8) {
        float4 av = make_float4(0.f, 0.f, 0.f, 0.f);
        int gr = row0 + aRow;
        if (gr < M) av = *(const float4*)&A[(long)gr * KD + k0 + aCol];
        As[aCol + 0][aRow] = av.x;
        As[aCol + 1][aRow] = av.y;
        As[aCol + 2][aRow] = av.z;
        As[aCol + 3][aRow] = av.w;
        float4 bv = *(const float4*)&B[(long)(k0 + bRow) * KD + col0 + bCol];
        *(float4*)&Bs[bRow][bCol] = bv;
        __syncthreads();
#pragma unroll
        for (int k = 0; k < 8; k++) {
            float a[8], b[8];
            *(float4*)&a[0] = *(const float4*)&As[k][ty * 8];
            *(float4*)&a[4] = *(const float4*)&As[k][ty * 8 + 4];
            *(float4*)&b[0] = *(const float4*)&Bs[k][tx * 8];
            *(float4*)&b[4] = *(const float4*)&Bs[k][tx * 8 + 4];
#pragma unroll
            for (int i = 0; i < 8; i++)
#pragma unroll
                for (int j = 0; j < 8; j++) acc[i][j] += a[i] * b[j];
        }
        __syncthreads();
    }
    // unguarded stores into padded scratch
#pragma unroll
    for (int i = 0; i < 8; i++) {
        int row = row0 + ty * 8 + i;
        float4 v0 = make_float4(acc[i][0], acc[i][1], acc[i][2], acc[i][3]);
        float4 v1 = make_float4(acc[i][4], acc[i][5], acc[i][6], acc[i][7]);
        *(float4*)&g_hs[(long)row * KD + col0 + tx * 8]     = v0;
        *(float4*)&g_hs[(long)row * KD + col0 + tx * 8 + 4] = v1;
    }
}

// ---------------- vd[k,h] = sum_c Wd[k, h*64+c] * ad[h*64+c] ----------------
__global__ void compute_vd_kernel(const float* __restrict__ Wd,
                                  const float* __restrict__ ad) {
    int idx = threadIdx.x;             // 1024 threads
    int k = idx >> 2;
    int h = idx & 3;
    float s = 0.f;
#pragma unroll 8
    for (int c = 0; c < 64; c++) s += Wd[k * KD + h * 64 + c] * ad[h * 64 + c];
    g_vd[k * 4 + h] = s;
}

// ---------------- a_s from g_hs, a_d = x . vd -------------------------------
__global__ void __launch_bounds__(256) compute_a_kernel(const float* __restrict__ X,
                                                        const float* __restrict__ attS) {
    __shared__ float r8[8];
    __shared__ float rr[8][4];
    int n = blockIdx.x;
    int t = threadIdx.x;
    int warp = t >> 5;
    int lane = t & 31;
    float xv = X[(long)n * KD + t];
    float hv = g_hs[(long)n * KD + t];
    // a_s partial (head = t>>6; each head = 2 warps)
    float sp = hv * attS[t];
#pragma unroll
    for (int off = 16; off > 0; off >>= 1) sp += __shfl_down_sync(0xffffffffu, sp, off);
    if (lane == 0) r8[warp] = sp;
    // a_d partials: each thread contributes to all 4 heads
#pragma unroll
    for (int h = 0; h < 4; h++) {
        float u = xv * g_vd[t * 4 + h];
#pragma unroll
        for (int off = 16; off > 0; off >>= 1) u += __shfl_down_sync(0xffffffffu, u, off);
        if (lane == 0) rr[warp][h] = u;
    }
    __syncthreads();
    if (t < 4) {
        g_as[n * 4 + t] = r8[2 * t] + r8[2 * t + 1];
        float s = 0.f;
#pragma unroll
        for (int w = 0; w < 8; w++) s += rr[w][t];
        g_ad[n * 4 + t] = s;
    }
}

// ---------------- per-layer init --------------------------------------------
__global__ void init_nh_kernel() {
    int i = blockIdx.x * blockDim.x + threadIdx.x;
    if (i < NNODES * HEADS) {
        g_amax[i] = 0u;       // below encf() of any finite/−inf value
        g_denom[i] = 0.f;
    }
}

// ---------------- edge pass A: alpha + atomic max ---------------------------
__global__ void edgeA_kernel(const int* __restrict__ src, const int* __restrict__ dst,
                             int e2) {
    int e = blockIdx.x * blockDim.x + threadIdx.x;
    if (e >= e2) return;
    int s = src[e], d = dst[e];
    float4 as4 = *(const float4*)&g_as[s * 4];
    float4 ad4 = *(const float4*)&g_ad[d * 4];
    float4 al;
    float v;
    v = as4.x + ad4.x; al.x = v > 0.f ? v : 0.2f * v;
    v = as4.y + ad4.y; al.y = v > 0.f ? v : 0.2f * v;
    v = as4.z + ad4.z; al.z = v > 0.f ? v : 0.2f * v;
    v = as4.w + ad4.w; al.w = v > 0.f ? v : 0.2f * v;
    g_w[e] = al;
    atomicMax(&g_amax[d * 4 + 0], encf(al.x));
    atomicMax(&g_amax[d * 4 + 1], encf(al.y));
    atomicMax(&g_amax[d * 4 + 2], encf(al.z));
    atomicMax(&g_amax[d * 4 + 3], encf(al.w));
}

// ---------------- edge pass B: exp + denom ----------------------------------
__global__ void edgeB_kernel(const int* __restrict__ dst, int e2) {
    int e = blockIdx.x * blockDim.x + threadIdx.x;
    if (e >= e2) return;
    int d = dst[e];
    float4 al = g_w[e];
    float4 ex;
    ex.x = __expf(al.x - decf(g_amax[d * 4 + 0]));
    ex.y = __expf(al.y - decf(g_amax[d * 4 + 1]));
    ex.z = __expf(al.z - decf(g_amax[d * 4 + 2]));
    ex.w = __expf(al.w - decf(g_amax[d * 4 + 3]));
    g_w[e] = ex;
    atomicAdd(&g_denom[d * 4 + 0], ex.x);
    atomicAdd(&g_denom[d * 4 + 1], ex.y);
    atomicAdd(&g_denom[d * 4 + 2], ex.z);
    atomicAdd(&g_denom[d * 4 + 3], ex.w);
}

// ---------------- aggregation (block per node) ------------------------------
// mode 0: out[n,256] = elu(acc/denom + bias)
// mode 1: head-mean -> + b2 -> log_softmax over 64 -> out[n,64]
__global__ void __launch_bounds__(256) aggregate_kernel(const int* __restrict__ src,
                                                        const float* __restrict__ bias,
                                                        float* __restrict__ out,
                                                        int mode) {
    __shared__ int    s_src[32];
    __shared__ float4 s_ex[32];
    __shared__ float  s_den[4];
    __shared__ float  sh[256];
    __shared__ float  s_red[2];

    int n = blockIdx.x;
    int t = threadIdx.x;
    int head = t >> 6;
    int base = g_rowptr[n];
    int deg = g_rowptr[n + 1] - base;

    if (t < 4) s_den[t] = g_denom[n * 4 + t] + 1e-16f;
    __syncthreads();

    float acc = 0.f;
    for (int cs = 0; cs < deg; cs += 32) {
        int m = deg - cs; if (m > 32) m = 32;
        if (t < m) {
            int eid = g_eids[base + cs + t];
            s_src[t] = src[eid];
            s_ex[t] = g_w[eid];
        }
        __syncthreads();
#pragma unroll 4
        for (int i = 0; i < m; i++) {
            float e = ((const float*)&s_ex[i])[head];   // warp-broadcast
            acc += e * g_hs[(long)s_src[i] * KD + t];
        }
        __syncthreads();
    }

    float v = acc / s_den[head];
    if (mode == 0) {
        v += bias[t];
        v = v > 0.f ? v : expm1f(v);
        out[(long)n * KD + t] = v;
    } else {
        sh[t] = v;
        __syncthreads();
        if (t < 64) sh[t] = 0.25f * (sh[t] + sh[t + 64] + sh[t + 128] + sh[t + 192]) + bias[t];
        __syncthreads();
        if (t < 32) {
            float a = fmaxf(sh[t], sh[t + 32]);
#pragma unroll
            for (int off = 16; off > 0; off >>= 1)
                a = fmaxf(a, __shfl_xor_sync(0xffffffffu, a, off));
            if (t == 0) s_red[0] = a;
        }
        __syncthreads();
        if (t < 32) {
            float mx = s_red[0];
            float a = expf(sh[t] - mx) + expf(sh[t + 32] - mx);
#pragma unroll
            for (int off = 16; off > 0; off >>= 1)
                a += __shfl_xor_sync(0xffffffffu, a, off);
            if (t == 0) s_red[1] = a;
        }
        __syncthreads();
        if (t < 64) out[(long)n * 64 + t] = sh[t] - s_red[0] - logf(s_red[1]);
    }
}

// ---------------- launch -----------------------------------------------------
extern "C" void kernel_launch(void* const* d_in, const int* in_sizes, int n_in,
                              void* d_out, int out_size) {
    const float* x = (const float*)d_in[0];
    const int* ei = (const int*)d_in[1];
    int e2 = in_sizes[1] / 2;
    const int* src = ei;
    const int* dstp = ei + e2;
    const float* Ws[3] = {(const float*)d_in[2], (const float*)d_in[7],  (const float*)d_in[12]};
    const float* Wd[3] = {(const float*)d_in[3], (const float*)d_in[8],  (const float*)d_in[13]};
    const float* As[3] = {(const float*)d_in[4], (const float*)d_in[9],  (const float*)d_in[14]};
    const float* Ad[3] = {(const float*)d_in[5], (const float*)d_in[10], (const float*)d_in[15]};
    const float* Bb[3] = {(const float*)d_in[6], (const float*)d_in[11], (const float*)d_in[16]};
    float* out = (float*)d_out;

    float* bufPtr = 0;
    cudaGetSymbolAddress((void**)&bufPtr, g_buf);

    int gE = (e2 + 255) / 256;

    // CSR by destination (built fresh each call; graph is fixed input)
    clear_deg_kernel<<<(NNODES + 255) / 256, 256>>>();
    count_deg_kernel<<<gE, 256>>>(dstp, e2);
    scan_kernel<<<1, 1024>>>();
    scatter_kernel<<<gE, 256>>>(dstp, e2);

    for (int l = 0; l < 3; l++) {
        const float* Ain = (l == 0) ? x : bufPtr;
        gemm_kernel<<<dim3(MPAD / 128, 2), 256>>>(Ain, Ws[l], NNODES);
        compute_vd_kernel<<<1, 1024>>>(Wd[l], Ad[l]);
        compute_a_kernel<<<NNODES, 256>>>(Ain, As[l]);
        init_nh_kernel<<<(NNODES * HEADS + 255) / 256, 256>>>();
        edgeA_kernel<<<gE, 256>>>(src, dstp, e2);
        edgeB_kernel<<<gE, 256>>>(dstp, e2);
        if (l < 2) aggregate_kernel<<<NNODES, 256>>>(src, Bb[l], bufPtr, 0);
        else       aggregate_kernel<<<NNODES, 256>>>(src, Bb[l], out, 1);
    }
}

// round 3
// speedup vs baseline: 1.2667x; 1.2667x over previous
#include <cuda_runtime.h>
#include <cuda_bf16.h>
#include <math.h>
#include <stdint.h>

#define NNODES 50000
#define MPAD   50048      // 391 * 128
#define KD     256
#define HEADS  4
#define EMAX   1700000

// ---------------- device scratch --------------------------------------------
__device__ float          g_hs[MPAD * KD];      // source transform (fp32)
__device__ float          g_buf[MPAD * KD];     // layer activations (fp32)
__device__ __nv_bfloat16  g_Ahi[MPAD * KD];     // activation split hi
__device__ __nv_bfloat16  g_Alo[MPAD * KD];     // activation split lo
__device__ __nv_bfloat16  g_Bthi[KD * KD];      // W^T split hi  [n][k]
__device__ __nv_bfloat16  g_Btlo[KD * KD];      // W^T split lo  [n][k]
__device__ float          g_as[NNODES * HEADS];
__device__ float          g_ad[NNODES * HEADS];
__device__ float          g_vd[KD * HEADS];     // Wd @ att_d, [k][h]
__device__ float          g_denom[NNODES * HEADS];
__device__ int            g_deg[NNODES];
__device__ int            g_rowptr[NNODES + 1];
__device__ int            g_cursor[NNODES];
__device__ int            g_eids[EMAX];

// ---------------- bf16 split helpers ----------------------------------------
__device__ __forceinline__ void split_pair(float a, float b, unsigned& hi, unsigned& lo) {
    __nv_bfloat16 ha = __float2bfloat16(a), hb = __float2bfloat16(b);
    float ra = a - __bfloat162float(ha);
    float rb = b - __bfloat162float(hb);
    __nv_bfloat162 h2 = __halves2bfloat162(ha, hb);
    __nv_bfloat162 l2 = __floats2bfloat162_rn(ra, rb);
    hi = *reinterpret_cast<unsigned*>(&h2);
    lo = *reinterpret_cast<unsigned*>(&l2);
}

// ---------------- mma.sync bf16 (sm_80+ path; legal on plain sm_100) --------
__device__ __forceinline__ void mma_bf16(float* c, const uint32_t* a, const uint32_t* b) {
    asm volatile(
        "mma.sync.aligned.m16n8k16.row.col.f32.bf16.bf16.f32 "
        "{%0,%1,%2,%3},{%4,%5,%6,%7},{%8,%9},{%0,%1,%2,%3};"
        : "+f"(c[0]), "+f"(c[1]), "+f"(c[2]), "+f"(c[3])
        : "r"(a[0]), "r"(a[1]), "r"(a[2]), "r"(a[3]), "r"(b[0]), "r"(b[1]));
}

// ---------------- CSR build --------------------------------------------------
__global__ void clear_deg_kernel() {
    int i = blockIdx.x * blockDim.x + threadIdx.x;
    if (i < NNODES) g_deg[i] = 0;
}
__global__ void count_deg_kernel(const int* __restrict__ dst, int e2) {
    int e = blockIdx.x * blockDim.x + threadIdx.x;
    if (e < e2) atomicAdd(&g_deg[dst[e]], 1);
}
__global__ void scan_kernel() {
    __shared__ int s[1024];
    int t = threadIdx.x;
    const int per = (NNODES + 1023) / 1024;
    int start = t * per;
    int end = start + per; if (end > NNODES) end = NNODES;
    int sum = 0;
    for (int i = start; i < end; i++) sum += g_deg[i];
    s[t] = sum;
    __syncthreads();
    for (int off = 1; off < 1024; off <<= 1) {
        int v = (t >= off) ? s[t - off] : 0;
        __syncthreads();
        s[t] += v;
        __syncthreads();
    }
    int run = (t > 0) ? s[t - 1] : 0;
    for (int i = start; i < end; i++) {
        int d = g_deg[i];
        g_rowptr[i] = run;
        g_cursor[i] = run;
        run += d;
    }
    if (t == 0) g_rowptr[NNODES] = s[1023];
}
__global__ void scatter_kernel(const int* __restrict__ dst, int e2) {
    int e = blockIdx.x * blockDim.x + threadIdx.x;
    if (e < e2) {
        int pos = atomicAdd(&g_cursor[dst[e]], 1);
        g_eids[pos] = e;
    }
}

// ---------------- A pre-split: fp32 -> bf16 hi/lo ----------------------------
__global__ void split_kernel(const float* __restrict__ A, int nf4) {
    int i = blockIdx.x * blockDim.x + threadIdx.x;
    if (i >= nf4) return;
    float4 v = ((const float4*)A)[i];
    uint2 h, l;
    split_pair(v.x, v.y, h.x, l.x);
    split_pair(v.z, v.w, h.y, l.y);
    ((uint2*)g_Ahi)[i] = h;
    ((uint2*)g_Alo)[i] = l;
}

// ---------------- B transpose+split: W[k][n] -> g_Bt*[n][k] ------------------
__global__ void btsplit_kernel(const float* __restrict__ W) {
    int i = blockIdx.x * blockDim.x + threadIdx.x;   // 65536 threads
    int n = i >> 8, k = i & 255;
    float v = W[k * KD + n];
    __nv_bfloat16 h = __float2bfloat16(v);
    g_Bthi[i] = h;
    g_Btlo[i] = __float2bfloat16(v - __bfloat162float(h));
}

// ---------------- vd[k,h] = sum_c Wd[k, h*64+c] * ad[h*64+c] -----------------
__global__ void compute_vd_kernel(const float* __restrict__ Wd,
                                  const float* __restrict__ ad) {
    int idx = threadIdx.x;             // 1024 threads
    int k = idx >> 2;
    int h = idx & 3;
    float s = 0.f;
#pragma unroll 8
    for (int c = 0; c < 64; c++) s += Wd[k * KD + h * 64 + c] * ad[h * 64 + c];
    g_vd[k * 4 + h] = s;
}

// ---------------- tensor-core GEMM: g_hs = A @ W (3-product bf16 split) ------
// grid (391, 2), 256 threads (8 warps). CTA tile 128x128, BK=32.
// Warp tile 64x32: warp_m = wid>>2 (2), warp_n = wid&3 (4).
// Smem row stride 20 words (conflict-free for the m16n8k16 fragment pattern).
#define S32 20
__global__ void __launch_bounds__(256) gemm_mma_kernel() {
    __shared__ uint32_t sAh[128 * S32], sAl[128 * S32];
    __shared__ uint32_t sBh[128 * S32], sBl[128 * S32];
    const int tid = threadIdx.x;
    const int wid = tid >> 5, lane = tid & 31;
    const int wm = wid >> 2, wn = wid & 3;
    const int row0 = blockIdx.x * 128;
    const int n0 = blockIdx.y * 128;
    const int g8 = lane >> 2, tq = lane & 3;

    float c[4][4][4];
#pragma unroll
    for (int mt = 0; mt < 4; mt++)
#pragma unroll
        for (int nt = 0; nt < 4; nt++)
#pragma unroll
            for (int j = 0; j < 4; j++) c[mt][nt][j] = 0.f;

    for (int k0 = 0; k0 < KD; k0 += 32) {
        // global -> smem: 512 uint4 per array; 2 per thread per array
#pragma unroll
        for (int i = 0; i < 2; i++) {
            int idx = tid + i * 256;
            int r = idx >> 2, c4 = idx & 3;
            long ga = (long)(row0 + r) * KD + k0 + c4 * 8;
            long gb = (long)(n0 + r) * KD + k0 + c4 * 8;
            int so = r * S32 + c4 * 4;
            uint4 v;
            v = *(const uint4*)(g_Ahi + ga);
            *(uint2*)&sAh[so] = make_uint2(v.x, v.y);
            *(uint2*)&sAh[so + 2] = make_uint2(v.z, v.w);
            v = *(const uint4*)(g_Alo + ga);
            *(uint2*)&sAl[so] = make_uint2(v.x, v.y);
            *(uint2*)&sAl[so + 2] = make_uint2(v.z, v.w);
            v = *(const uint4*)(g_Bthi + gb);
            *(uint2*)&sBh[so] = make_uint2(v.x, v.y);
            *(uint2*)&sBh[so + 2] = make_uint2(v.z, v.w);
            v = *(const uint4*)(g_Btlo + gb);
            *(uint2*)&sBl[so] = make_uint2(v.x, v.y);
            *(uint2*)&sBl[so + 2] = make_uint2(v.z, v.w);
        }
        __syncthreads();
#pragma unroll
        for (int kk = 0; kk < 2; kk++) {
            const int kb = kk * 8;
            uint32_t ah[4][4], al[4][4], bh[4][2], bl[4][2];
#pragma unroll
            for (int mt = 0; mt < 4; mt++) {
                int r = (wm * 64 + mt * 16 + g8) * S32 + kb + tq;
                int r8 = r + 8 * S32;
                ah[mt][0] = sAh[r];     ah[mt][1] = sAh[r8];
                ah[mt][2] = sAh[r + 4]; ah[mt][3] = sAh[r8 + 4];
                al[mt][0] = sAl[r];     al[mt][1] = sAl[r8];
                al[mt][2] = sAl[r + 4]; al[mt][3] = sAl[r8 + 4];
            }
#pragma unroll
            for (int nt = 0; nt < 4; nt++) {
                int r = (wn * 32 + nt * 8 + g8) * S32 + kb + tq;
                bh[nt][0] = sBh[r]; bh[nt][1] = sBh[r + 4];
                bl[nt][0] = sBl[r]; bl[nt][1] = sBl[r + 4];
            }
#pragma unroll
            for (int mt = 0; mt < 4; mt++)
#pragma unroll
                for (int nt = 0; nt < 4; nt++) {
                    mma_bf16(c[mt][nt], ah[mt], bh[nt]);
                    mma_bf16(c[mt][nt], ah[mt], bl[nt]);
                    mma_bf16(c[mt][nt], al[mt], bh[nt]);
                }
        }
        __syncthreads();
    }
    // epilogue: fragment -> g_hs
#pragma unroll
    for (int mt = 0; mt < 4; mt++) {
        int r = row0 + wm * 64 + mt * 16 + g8;
#pragma unroll
        for (int nt = 0; nt < 4; nt++) {
            int col = n0 + wn * 32 + nt * 8 + tq * 2;
            *(float2*)&g_hs[(long)r * KD + col] = make_float2(c[mt][nt][0], c[mt][nt][1]);
            *(float2*)&g_hs[(long)(r + 8) * KD + col] = make_float2(c[mt][nt][2], c[mt][nt][3]);
        }
    }
}

// ---------------- a_s = hs . attS, a_d = x . vd  (warp per node) -------------
__global__ void __launch_bounds__(256) atts_kernel(const float* __restrict__ X,
                                                   const float* __restrict__ attS) {
    __shared__ float svd[KD * 4];
    __shared__ float satt[KD];
    int tid = threadIdx.x;
    for (int i = tid; i < KD * 4; i += 256) svd[i] = g_vd[i];
    satt[tid] = attS[tid];
    __syncthreads();
    int warp = tid >> 5, lane = tid & 31;
    int n = blockIdx.x * 8 + warp;
    if (n >= NNODES) return;
    const float4* hs4 = (const float4*)&g_hs[(long)n * KD];
    const float4* x4 = (const float4*)X + (long)n * 64;
    float s = 0.f, a0 = 0.f, a1 = 0.f, a2 = 0.f, a3 = 0.f;
#pragma unroll
    for (int g4 = 0; g4 < 2; g4++) {
        float4 hv = hs4[lane * 2 + g4];
        int cc = lane * 8 + g4 * 4;
        s += hv.x * satt[cc] + hv.y * satt[cc + 1] + hv.z * satt[cc + 2] + hv.w * satt[cc + 3];
        float4 xv = x4[lane * 2 + g4];
        const float* p = &svd[cc * 4];
        a0 += xv.x * p[0] + xv.y * p[4] + xv.z * p[8]  + xv.w * p[12];
        a1 += xv.x * p[1] + xv.y * p[5] + xv.z * p[9]  + xv.w * p[13];
        a2 += xv.x * p[2] + xv.y * p[6] + xv.z * p[10] + xv.w * p[14];
        a3 += xv.x * p[3] + xv.y * p[7] + xv.z * p[11] + xv.w * p[15];
    }
    // a_s: reduce within 8-lane groups (one head per group)
#pragma unroll
    for (int off = 4; off > 0; off >>= 1) s += __shfl_down_sync(0xffffffffu, s, off, 8);
    if ((lane & 7) == 0) g_as[n * 4 + (lane >> 3)] = s;
    // a_d: full-warp reduce of 4 head accumulators
#pragma unroll
    for (int off = 16; off > 0; off >>= 1) {
        a0 += __shfl_xor_sync(0xffffffffu, a0, off);
        a1 += __shfl_xor_sync(0xffffffffu, a1, off);
        a2 += __shfl_xor_sync(0xffffffffu, a2, off);
        a3 += __shfl_xor_sync(0xffffffffu, a3, off);
    }
    if (lane == 0) ((float4*)g_ad)[n] = make_float4(a0, a1, a2, a3);
}

// ---------------- edge pass: denom += exp(leakyrelu(a_s+a_d)) ----------------
// No max-stabilizer: softmax ratio is shift-invariant; alpha is O(1).
__global__ void edge_denom_kernel(const int* __restrict__ src,
                                  const int* __restrict__ dst, int e2) {
    int e = blockIdx.x * blockDim.x + threadIdx.x;
    if (e >= e2) return;
    int s = src[e], d = dst[e];
    float4 as4 = ((const float4*)g_as)[s];
    float4 ad4 = ((const float4*)g_ad)[d];
    float v;
    v = as4.x + ad4.x; v = v > 0.f ? v : 0.2f * v;
    float e0 = __expf(v);
    v = as4.y + ad4.y; v = v > 0.f ? v : 0.2f * v;
    float e1 = __expf(v);
    v = as4.z + ad4.z; v = v > 0.f ? v : 0.2f * v;
    float e2f = __expf(v);
    v = as4.w + ad4.w; v = v > 0.f ? v : 0.2f * v;
    float e3 = __expf(v);
    atomicAdd(&g_denom[d * 4 + 0], e0);
    atomicAdd(&g_denom[d * 4 + 1], e1);
    atomicAdd(&g_denom[d * 4 + 2], e2f);
    atomicAdd(&g_denom[d * 4 + 3], e3);
}

// ---------------- aggregation (block per node), exp recomputed ---------------
__global__ void __launch_bounds__(256) aggregate_kernel(const int* __restrict__ src,
                                                        const float* __restrict__ bias,
                                                        float* __restrict__ out,
                                                        int mode) {
    __shared__ int    s_src[32];
    __shared__ float4 s_ex[32];
    __shared__ float  s_den[4];
    __shared__ float4 s_ad4;
    __shared__ float  sh[256];
    __shared__ float  s_red[2];

    int n = blockIdx.x;
    int t = threadIdx.x;
    int head = t >> 6;
    int base = g_rowptr[n];
    int deg = g_rowptr[n + 1] - base;

    if (t == 0) s_ad4 = ((const float4*)g_ad)[n];
    if (t < 4) s_den[t] = g_denom[n * 4 + t] + 1e-16f;
    __syncthreads();
    float4 ad4 = s_ad4;

    float acc = 0.f;
    for (int cs = 0; cs < deg; cs += 32) {
        int m = deg - cs; if (m > 32) m = 32;
        if (t < m) {
            int eid = g_eids[base + cs + t];
            int s = src[eid];
            s_src[t] = s;
            float4 a = ((const float4*)g_as)[s];
            float v; float4 ex;
            v = a.x + ad4.x; v = v > 0.f ? v : 0.2f * v; ex.x = __expf(v);
            v = a.y + ad4.y; v = v > 0.f ? v : 0.2f * v; ex.y = __expf(v);
            v = a.z + ad4.z; v = v > 0.f ? v : 0.2f * v; ex.z = __expf(v);
            v = a.w + ad4.w; v = v > 0.f ? v : 0.2f * v; ex.w = __expf(v);
            s_ex[t] = ex;
        }
        __syncthreads();
#pragma unroll 4
        for (int i = 0; i < m; i++) {
            float e = ((const float*)&s_ex[i])[head];
            acc += e * g_hs[(long)s_src[i] * KD + t];
        }
        __syncthreads();
    }

    float v = acc / s_den[head];
    if (mode == 0) {
        v += bias[t];
        v = v > 0.f ? v : expm1f(v);
        out[(long)n * KD + t] = v;
    } else {
        sh[t] = v;
        __syncthreads();
        if (t < 64) sh[t] = 0.25f * (sh[t] + sh[t + 64] + sh[t + 128] + sh[t + 192]) + bias[t];
        __syncthreads();
        if (t < 32) {
            float a = fmaxf(sh[t], sh[t + 32]);
#pragma unroll
            for (int off = 16; off > 0; off >>= 1)
                a = fmaxf(a, __shfl_xor_sync(0xffffffffu, a, off));
            if (t == 0) s_red[0] = a;
        }
        __syncthreads();
        if (t < 32) {
            float mx = s_red[0];
            float a = expf(sh[t] - mx) + expf(sh[t + 32] - mx);
#pragma unroll
            for (int off = 16; off > 0; off >>= 1)
                a += __shfl_xor_sync(0xffffffffu, a, off);
            if (t == 0) s_red[1] = a;
        }
        __syncthreads();
        if (t < 64) out[(long)n * 64 + t] = sh[t] - s_red[0] - logf(s_red[1]);
    }
}

// ---------------- launch -----------------------------------------------------
extern "C" void kernel_launch(void* const* d_in, const int* in_sizes, int n_in,
                              void* d_out, int out_size) {
    const float* x = (const float*)d_in[0];
    const int* ei = (const int*)d_in[1];
    int e2 = in_sizes[1] / 2;
    const int* src = ei;
    const int* dstp = ei + e2;
    const float* Ws[3] = {(const float*)d_in[2], (const float*)d_in[7],  (const float*)d_in[12]};
    const float* Wd[3] = {(const float*)d_in[3], (const float*)d_in[8],  (const float*)d_in[13]};
    const float* As[3] = {(const float*)d_in[4], (const float*)d_in[9],  (const float*)d_in[14]};
    const float* Ad[3] = {(const float*)d_in[5], (const float*)d_in[10], (const float*)d_in[15]};
    const float* Bb[3] = {(const float*)d_in[6], (const float*)d_in[11], (const float*)d_in[16]};
    float* out = (float*)d_out;

    float* bufPtr = 0;   cudaGetSymbolAddress((void**)&bufPtr, g_buf);
    float* denomPtr = 0; cudaGetSymbolAddress((void**)&denomPtr, g_denom);

    int gE = (e2 + 255) / 256;

    // CSR by destination
    clear_deg_kernel<<<(NNODES + 255) / 256, 256>>>();
    count_deg_kernel<<<gE, 256>>>(dstp, e2);
    scan_kernel<<<1, 1024>>>();
    scatter_kernel<<<gE, 256>>>(dstp, e2);

    for (int l = 0; l < 3; l++) {
        const float* Ain = (l == 0) ? x : bufPtr;
        int nf4 = NNODES * KD / 4;
        split_kernel<<<(nf4 + 255) / 256, 256>>>(Ain, nf4);
        btsplit_kernel<<<KD * KD / 256, 256>>>(Ws[l]);
        compute_vd_kernel<<<1, 1024>>>(Wd[l], Ad[l]);
        gemm_mma_kernel<<<dim3(MPAD / 128, 2), 256>>>();
        atts_kernel<<<(NNODES + 7) / 8, 256>>>(Ain, As[l]);
        cudaMemsetAsync(denomPtr, 0, NNODES * HEADS * sizeof(float));
        edge_denom_kernel<<<gE, 256>>>(src, dstp, e2);
        if (l < 2) aggregate_kernel<<<NNODES, 256>>>(src, Bb[l], bufPtr, 0);
        else       aggregate_kernel<<<NNODES, 256>>>(src, Bb[l], out, 1);
    }
}

// round 4
// speedup vs baseline: 1.7257x; 1.3623x over previous
#include <cuda_runtime.h>
#include <cuda_bf16.h>
#include <math.h>
#include <stdint.h>

#define NNODES 50000
#define MPAD   50048      // 391 * 128
#define KD     256
#define HEADS  4
#define EMAX   1700000

// ---------------- device scratch --------------------------------------------
__device__ float          g_hs[MPAD * KD];      // source transform (fp32)
__device__ __nv_bfloat16  g_Ahi[MPAD * KD];     // activation split hi
__device__ __nv_bfloat16  g_Alo[MPAD * KD];     // activation split lo
__device__ __nv_bfloat16  g_Bthi[KD * KD];      // W^T split hi  [n][k]
__device__ __nv_bfloat16  g_Btlo[KD * KD];      // W^T split lo  [n][k]
__device__ float          g_as[MPAD * HEADS];
__device__ float          g_ad[NNODES * HEADS];
__device__ float          g_vd[3 * KD * HEADS]; // Wd_l @ att_d_l, [l][k][h]
__device__ float          g_denom[NNODES * HEADS];
__device__ int            g_deg[NNODES];
__device__ int            g_rowptr[NNODES + 1];
__device__ int            g_cursor[NNODES];
__device__ int            g_eids[EMAX];

// ---------------- helpers ----------------------------------------------------
__device__ __forceinline__ void split_pair(float a, float b, unsigned& hi, unsigned& lo) {
    __nv_bfloat16 ha = __float2bfloat16(a), hb = __float2bfloat16(b);
    float ra = a - __bfloat162float(ha);
    float rb = b - __bfloat162float(hb);
    __nv_bfloat162 h2 = __halves2bfloat162(ha, hb);
    __nv_bfloat162 l2 = __floats2bfloat162_rn(ra, rb);
    hi = *reinterpret_cast<unsigned*>(&h2);
    lo = *reinterpret_cast<unsigned*>(&l2);
}

__device__ __forceinline__ void mma_bf16(float* c, const uint32_t* a, const uint32_t* b) {
    asm volatile(
        "mma.sync.aligned.m16n8k16.row.col.f32.bf16.bf16.f32 "
        "{%0,%1,%2,%3},{%4,%5,%6,%7},{%8,%9},{%0,%1,%2,%3};"
        : "+f"(c[0]), "+f"(c[1]), "+f"(c[2]), "+f"(c[3])
        : "r"(a[0]), "r"(a[1]), "r"(a[2]), "r"(a[3]), "r"(b[0]), "r"(b[1]));
}

#define CP_ASYNC16(dst_u32, src_ptr) \
    asm volatile("cp.async.cg.shared.global [%0], [%1], 16;" \
                 :: "r"(dst_u32), "l"(src_ptr))
#define CP_COMMIT() asm volatile("cp.async.commit_group;" ::: "memory")
#define CP_WAIT0()  asm volatile("cp.async.wait_group 0;" ::: "memory")

// ---------------- CSR build --------------------------------------------------
__global__ void clear_deg_kernel() {
    int i = blockIdx.x * blockDim.x + threadIdx.x;
    if (i < NNODES) g_deg[i] = 0;
}
__global__ void count_deg_kernel(const int* __restrict__ dst, int e2) {
    int e = blockIdx.x * blockDim.x + threadIdx.x;
    if (e < e2) atomicAdd(&g_deg[dst[e]], 1);
}
__global__ void scan_kernel() {
    __shared__ int s[1024];
    int t = threadIdx.x;
    const int per = (NNODES + 1023) / 1024;
    int start = t * per;
    int end = start + per; if (end > NNODES) end = NNODES;
    int sum = 0;
    for (int i = start; i < end; i++) sum += g_deg[i];
    s[t] = sum;
    __syncthreads();
    for (int off = 1; off < 1024; off <<= 1) {
        int v = (t >= off) ? s[t - off] : 0;
        __syncthreads();
        s[t] += v;
        __syncthreads();
    }
    int run = (t > 0) ? s[t - 1] : 0;
    for (int i = start; i < end; i++) {
        int d = g_deg[i];
        g_rowptr[i] = run;
        g_cursor[i] = run;
        run += d;
    }
    if (t == 0) g_rowptr[NNODES] = s[1023];
}
__global__ void scatter_kernel(const int* __restrict__ dst, int e2) {
    int e = blockIdx.x * blockDim.x + threadIdx.x;
    if (e < e2) {
        int pos = atomicAdd(&g_cursor[dst[e]], 1);
        g_eids[pos] = e;
    }
}

// ---------------- layer-0 pre-split: x -> bf16 hi/lo -------------------------
__global__ void split_x_kernel(const float* __restrict__ A, int nf4) {
    int i = blockIdx.x * blockDim.x + threadIdx.x;
    if (i >= nf4) return;
    float4 v = ((const float4*)A)[i];
    uint2 h, l;
    split_pair(v.x, v.y, h.x, l.x);
    split_pair(v.z, v.w, h.y, l.y);
    ((uint2*)g_Ahi)[i] = h;
    ((uint2*)g_Alo)[i] = l;
}

// ---------------- B transpose+split: W[k][n] -> g_Bt*[n][k] ------------------
__global__ void btsplit_kernel(const float* __restrict__ W) {
    int i = blockIdx.x * blockDim.x + threadIdx.x;   // 65536 threads
    int n = i >> 8, k = i & 255;
    float v = W[k * KD + n];
    __nv_bfloat16 h = __float2bfloat16(v);
    g_Bthi[i] = h;
    g_Btlo[i] = __float2bfloat16(v - __bfloat162float(h));
}

// ---------------- vd[l][k][h] = sum_c Wd_l[k, h*64+c] * ad_l[h*64+c] ---------
__global__ void compute_vd_kernel(const float* __restrict__ Wd,
                                  const float* __restrict__ ad, int loff) {
    int idx = threadIdx.x;             // 1024 threads
    int k = idx >> 2;
    int h = idx & 3;
    float s = 0.f;
#pragma unroll 8
    for (int c = 0; c < 64; c++) s += Wd[k * KD + h * 64 + c] * ad[h * 64 + c];
    g_vd[loff + k * 4 + h] = s;
}

// ---------------- layer-0 a_d = x . vd0  (warp per node) ---------------------
__global__ void __launch_bounds__(256) ad0_kernel(const float* __restrict__ X) {
    __shared__ float svd[KD * 4];
    int tid = threadIdx.x;
    for (int i = tid; i < KD * 4; i += 256) svd[i] = g_vd[i];
    __syncthreads();
    int warp = tid >> 5, lane = tid & 31;
    int n = blockIdx.x * 8 + warp;
    if (n >= NNODES) return;
    const float4* x4 = (const float4*)X + (long)n * 64;
    float a0 = 0.f, a1 = 0.f, a2 = 0.f, a3 = 0.f;
#pragma unroll
    for (int g4 = 0; g4 < 2; g4++) {
        float4 xv = x4[lane * 2 + g4];
        const float* p = &svd[(lane * 8 + g4 * 4) * 4];
        a0 += xv.x * p[0] + xv.y * p[4] + xv.z * p[8]  + xv.w * p[12];
        a1 += xv.x * p[1] + xv.y * p[5] + xv.z * p[9]  + xv.w * p[13];
        a2 += xv.x * p[2] + xv.y * p[6] + xv.z * p[10] + xv.w * p[14];
        a3 += xv.x * p[3] + xv.y * p[7] + xv.z * p[11] + xv.w * p[15];
    }
#pragma unroll
    for (int off = 16; off > 0; off >>= 1) {
        a0 += __shfl_xor_sync(0xffffffffu, a0, off);
        a1 += __shfl_xor_sync(0xffffffffu, a1, off);
        a2 += __shfl_xor_sync(0xffffffffu, a2, off);
        a3 += __shfl_xor_sync(0xffffffffu, a3, off);
    }
    if (lane == 0) ((float4*)g_ad)[n] = make_float4(a0, a1, a2, a3);
}

// ---------------- GEMM: g_hs = A @ W (3-product bf16), cp.async 2-stage ------
// grid (391, 2), 256 threads. CTA tile 128x128, BK=32. Fused a_s epilogue.
#define S32 20
#define STAGE_W 10240        // words per stage: 4 arrays * 128*20
__global__ void __launch_bounds__(256) gemm_mma_kernel(const float* __restrict__ attS) {
    extern __shared__ uint32_t smem_u[];
    const int tid = threadIdx.x;
    const int wid = tid >> 5, lane = tid & 31;
    const int wm = wid >> 2, wn = wid & 3;
    const int row0 = blockIdx.x * 128;
    const int n0 = blockIdx.y * 128;
    const int g8 = lane >> 2, tq = lane & 3;
    const uint32_t smem_b = (uint32_t)__cvta_generic_to_shared(smem_u);

    // per-thread load geometry
    const int lr0 = tid >> 2;            // row 0..63  (i=0)
    const int lc4 = tid & 3;             // 16B group 0..3
    float c[4][4][4];
#pragma unroll
    for (int mt = 0; mt < 4; mt++)
#pragma unroll
        for (int nt = 0; nt < 4; nt++)
#pragma unroll
            for (int j = 0; j < 4; j++) c[mt][nt][j] = 0.f;

#define LOAD_CHUNK(stg, cc) do {                                               \
    int k0 = (cc) * 32;                                                        \
    _Pragma("unroll")                                                          \
    for (int i = 0; i < 2; i++) {                                              \
        int r = lr0 + i * 64;                                                  \
        long ga = (long)(row0 + r) * KD + k0 + lc4 * 8;                        \
        long gb = (long)(n0 + r) * KD + k0 + lc4 * 8;                          \
        uint32_t so = smem_b + ((stg) * STAGE_W + r * S32 + lc4 * 4) * 4;      \
        CP_ASYNC16(so,            g_Ahi + ga);                                 \
        CP_ASYNC16(so + 2560 * 4, g_Alo + ga);                                 \
        CP_ASYNC16(so + 5120 * 4, g_Bthi + gb);                                \
        CP_ASYNC16(so + 7680 * 4, g_Btlo + gb);                                \
    }                                                                          \
} while (0)

    LOAD_CHUNK(0, 0);
    CP_COMMIT();

    for (int cch = 0; cch < 8; cch++) {
        const int stg = cch & 1;
        CP_WAIT0();
        __syncthreads();
        if (cch < 7) { LOAD_CHUNK(stg ^ 1, cch + 1); CP_COMMIT(); }
        const uint32_t* sAh = smem_u + stg * STAGE_W;
        const uint32_t* sAl = sAh + 2560;
        const uint32_t* sBh = sAh + 5120;
        const uint32_t* sBl = sAh + 7680;
#pragma unroll
        for (int kk = 0; kk < 2; kk++) {
            const int kb = kk * 8;
            uint32_t ah[4][4], al[4][4], bh[4][2], bl[4][2];
#pragma unroll
            for (int mt = 0; mt < 4; mt++) {
                int r = (wm * 64 + mt * 16 + g8) * S32 + kb + tq;
                int r8 = r + 8 * S32;
                ah[mt][0] = sAh[r];     ah[mt][1] = sAh[r8];
                ah[mt][2] = sAh[r + 4]; ah[mt][3] = sAh[r8 + 4];
                al[mt][0] = sAl[r];     al[mt][1] = sAl[r8];
                al[mt][2] = sAl[r + 4]; al[mt][3] = sAl[r8 + 4];
            }
#pragma unroll
            for (int nt = 0; nt < 4; nt++) {
                int r = (wn * 32 + nt * 8 + g8) * S32 + kb + tq;
                bh[nt][0] = sBh[r]; bh[nt][1] = sBh[r + 4];
                bl[nt][0] = sBl[r]; bl[nt][1] = sBl[r + 4];
            }
#pragma unroll
            for (int mt = 0; mt < 4; mt++)
#pragma unroll
                for (int nt = 0; nt < 4; nt++) {
                    mma_bf16(c[mt][nt], ah[mt], bh[nt]);
                    mma_bf16(c[mt][nt], ah[mt], bl[nt]);
                    mma_bf16(c[mt][nt], al[mt], bh[nt]);
                }
        }
        __syncthreads();
    }

    // epilogue 1: fragments -> g_hs
#pragma unroll
    for (int mt = 0; mt < 4; mt++) {
        int r = row0 + wm * 64 + mt * 16 + g8;
#pragma unroll
        for (int nt = 0; nt < 4; nt++) {
            int col = n0 + wn * 32 + nt * 8 + tq * 2;
            *(float2*)&g_hs[(long)r * KD + col] = make_float2(c[mt][nt][0], c[mt][nt][1]);
            *(float2*)&g_hs[(long)(r + 8) * KD + col] = make_float2(c[mt][nt][2], c[mt][nt][3]);
        }
    }
    // epilogue 2: fused a_s partials (this warp covers 32 cols of one head)
    {
        float p0[4] = {0.f, 0.f, 0.f, 0.f};
        float p1[4] = {0.f, 0.f, 0.f, 0.f};
#pragma unroll
        for (int nt = 0; nt < 4; nt++) {
            int col = n0 + wn * 32 + nt * 8 + tq * 2;
            float a0 = attS[col], a1 = attS[col + 1];
#pragma unroll
            for (int mt = 0; mt < 4; mt++) {
                p0[mt] += c[mt][nt][0] * a0 + c[mt][nt][1] * a1;
                p1[mt] += c[mt][nt][2] * a0 + c[mt][nt][3] * a1;
            }
        }
        int head = blockIdx.y * 2 + (wn >> 1);
#pragma unroll
        for (int mt = 0; mt < 4; mt++) {
            p0[mt] += __shfl_xor_sync(0xffffffffu, p0[mt], 1);
            p0[mt] += __shfl_xor_sync(0xffffffffu, p0[mt], 2);
            p1[mt] += __shfl_xor_sync(0xffffffffu, p1[mt], 1);
            p1[mt] += __shfl_xor_sync(0xffffffffu, p1[mt], 2);
            if (tq == 0) {
                int r = row0 + wm * 64 + mt * 16 + g8;
                atomicAdd(&g_as[r * 4 + head], p0[mt]);
                atomicAdd(&g_as[(r + 8) * 4 + head], p1[mt]);
            }
        }
    }
}

// ---------------- edge pass: denom += exp(leakyrelu(a_s+a_d)) ----------------
__global__ void edge_denom_kernel(const int* __restrict__ src,
                                  const int* __restrict__ dst, int e2) {
    int e = blockIdx.x * blockDim.x + threadIdx.x;
    if (e >= e2) return;
    int s = src[e], d = dst[e];
    float4 as4 = ((const float4*)g_as)[s];
    float4 ad4 = ((const float4*)g_ad)[d];
    float v;
    v = as4.x + ad4.x; v = v > 0.f ? v : 0.2f * v;
    float e0 = __expf(v);
    v = as4.y + ad4.y; v = v > 0.f ? v : 0.2f * v;
    float e1 = __expf(v);
    v = as4.z + ad4.z; v = v > 0.f ? v : 0.2f * v;
    float e2f = __expf(v);
    v = as4.w + ad4.w; v = v > 0.f ? v : 0.2f * v;
    float e3 = __expf(v);
    atomicAdd(&g_denom[d * 4 + 0], e0);
    atomicAdd(&g_denom[d * 4 + 1], e1);
    atomicAdd(&g_denom[d * 4 + 2], e2f);
    atomicAdd(&g_denom[d * 4 + 3], e3);
}

// ---------------- aggregation: 128 thr/node, warp-per-head, float2 ----------
// mode 0: elu(acc/den + bias) -> split to Ahi/Alo; a_d(next) via vdn
// mode 1: head-mean + b2 + log_softmax -> out[n,64]
__global__ void __launch_bounds__(128) aggregate_kernel(const int* __restrict__ src,
                                                        const float* __restrict__ bias,
                                                        const float* __restrict__ vdn,
                                                        float* __restrict__ out,
                                                        int mode) {
    __shared__ float2 stage[4][32];
    __shared__ float  s_adp[4][4];
    __shared__ float  sh[256];
    __shared__ float  s_red[2];

    const int n = blockIdx.x;
    const int tid = threadIdx.x;
    const int w = tid >> 5, lane = tid & 31;
    const int base = g_rowptr[n];
    const int deg = g_rowptr[n + 1] - base;

    const float adw = g_ad[n * 4 + w];
    const float den = g_denom[n * 4 + w] + 1e-16f;

    const float2* __restrict__ hs2 = (const float2*)g_hs;
    const int colIdx = w * 32 + lane;     // float2 index within row

    float2 acc = make_float2(0.f, 0.f);
    for (int cs = 0; cs < deg; cs += 32) {
        int m = deg - cs; if (m > 32) m = 32;
        float ex = 0.f; int sI = 0;
        if (lane < m) {
            int eid = g_eids[base + cs + lane];
            sI = src[eid];
            float al = g_as[sI * 4 + w] + adw;
            al = al > 0.f ? al : 0.2f * al;
            ex = __expf(al);
        }
        stage[w][lane] = make_float2(ex, __int_as_float(sI));
        __syncwarp();
#pragma unroll 4
        for (int j = 0; j < m; j++) {
            float2 st = stage[w][j];
            int s = __float_as_int(st.y);
            float2 hv = hs2[s * 128 + colIdx];
            acc.x += st.x * hv.x;
            acc.y += st.x * hv.y;
        }
        __syncwarp();
    }

    const int col0 = w * 64 + lane * 2;
    float v0 = acc.x / den;
    float v1 = acc.y / den;
    if (mode == 0) {
        v0 += bias[col0];
        v1 += bias[col0 + 1];
        v0 = v0 > 0.f ? v0 : expm1f(v0);
        v1 = v1 > 0.f ? v1 : expm1f(v1);
        unsigned hi, lo;
        split_pair(v0, v1, hi, lo);
        ((uint32_t*)g_Ahi)[n * 128 + colIdx] = hi;
        ((uint32_t*)g_Alo)[n * 128 + colIdx] = lo;
        // a_d for next layer
        const float* p0 = &vdn[col0 * 4];
        float q0 = v0 * p0[0] + v1 * p0[4];
        float q1 = v0 * p0[1] + v1 * p0[5];
        float q2 = v0 * p0[2] + v1 * p0[6];
        float q3 = v0 * p0[3] + v1 * p0[7];
#pragma unroll
        for (int off = 16; off > 0; off >>= 1) {
            q0 += __shfl_xor_sync(0xffffffffu, q0, off);
            q1 += __shfl_xor_sync(0xffffffffu, q1, off);
            q2 += __shfl_xor_sync(0xffffffffu, q2, off);
            q3 += __shfl_xor_sync(0xffffffffu, q3, off);
        }
        if (lane < 4) {
            float q = lane == 0 ? q0 : lane == 1 ? q1 : lane == 2 ? q2 : q3;
            s_adp[w][lane] = q;
        }
        __syncthreads();
        if (tid < 4)
            g_ad[n * 4 + tid] = s_adp[0][tid] + s_adp[1][tid] + s_adp[2][tid] + s_adp[3][tid];
    } else {
        sh[col0] = v0;
        sh[col0 + 1] = v1;
        __syncthreads();
        if (tid < 64)
            sh[tid] = 0.25f * (sh[tid] + sh[tid + 64] + sh[tid + 128] + sh[tid + 192]) + bias[tid];
        __syncthreads();
        if (tid < 32) {
            float a = fmaxf(sh[tid], sh[tid + 32]);
#pragma unroll
            for (int off = 16; off > 0; off >>= 1)
                a = fmaxf(a, __shfl_xor_sync(0xffffffffu, a, off));
            if (tid == 0) s_red[0] = a;
        }
        __syncthreads();
        if (tid < 32) {
            float mx = s_red[0];
            float a = expf(sh[tid] - mx) + expf(sh[tid + 32] - mx);
#pragma unroll
            for (int off = 16; off > 0; off >>= 1)
                a += __shfl_xor_sync(0xffffffffu, a, off);
            if (tid == 0) s_red[1] = a;
        }
        __syncthreads();
        if (tid < 64) out[(long)n * 64 + tid] = sh[tid] - s_red[0] - logf(s_red[1]);
    }
}

// ---------------- launch -----------------------------------------------------
extern "C" void kernel_launch(void* const* d_in, const int* in_sizes, int n_in,
                              void* d_out, int out_size) {
    const float* x = (const float*)d_in[0];
    const int* ei = (const int*)d_in[1];
    int e2 = in_sizes[1] / 2;
    const int* src = ei;
    const int* dstp = ei + e2;
    const float* Ws[3] = {(const float*)d_in[2], (const float*)d_in[7],  (const float*)d_in[12]};
    const float* Wd[3] = {(const float*)d_in[3], (const float*)d_in[8],  (const float*)d_in[13]};
    const float* As[3] = {(const float*)d_in[4], (const float*)d_in[9],  (const float*)d_in[14]};
    const float* Ad[3] = {(const float*)d_in[5], (const float*)d_in[10], (const float*)d_in[15]};
    const float* Bb[3] = {(const float*)d_in[6], (const float*)d_in[11], (const float*)d_in[16]};
    float* out = (float*)d_out;

    float* asPtr = 0;    cudaGetSymbolAddress((void**)&asPtr, g_as);
    float* denomPtr = 0; cudaGetSymbolAddress((void**)&denomPtr, g_denom);
    float* vdPtr = 0;    cudaGetSymbolAddress((void**)&vdPtr, g_vd);

    const int GEMM_SMEM = 2 * STAGE_W * 4;   // 81920 B
    cudaFuncSetAttribute(gemm_mma_kernel, cudaFuncAttributeMaxDynamicSharedMemorySize,
                         GEMM_SMEM);

    int gE = (e2 + 255) / 256;

    // CSR by destination
    clear_deg_kernel<<<(NNODES + 255) / 256, 256>>>();
    count_deg_kernel<<<gE, 256>>>(dstp, e2);
    scan_kernel<<<1, 1024>>>();
    scatter_kernel<<<gE, 256>>>(dstp, e2);

    // one-time: x split, all vd, layer-0 a_d
    split_x_kernel<<<(NNODES * KD / 4 + 255) / 256, 256>>>(x, NNODES * KD / 4);
    for (int l = 0; l < 3; l++)
        compute_vd_kernel<<<1, 1024>>>(Wd[l], Ad[l], l * KD * HEADS);
    ad0_kernel<<<(NNODES + 7) / 8, 256>>>(x);

    for (int l = 0; l < 3; l++) {
        btsplit_kernel<<<KD * KD / 256, 256>>>(Ws[l]);
        cudaMemsetAsync(asPtr, 0, MPAD * HEADS * sizeof(float));
        gemm_mma_kernel<<<dim3(MPAD / 128, 2), 256, GEMM_SMEM>>>(As[l]);
        cudaMemsetAsync(denomPtr, 0, NNODES * HEADS * sizeof(float));
        edge_denom_kernel<<<gE, 256>>>(src, dstp, e2);
        if (l < 2)
            aggregate_kernel<<<NNODES, 128>>>(src, Bb[l], vdPtr + (l + 1) * KD * HEADS,
                                              (float*)0, 0);
        else
            aggregate_kernel<<<NNODES, 128>>>(src, Bb[l], vdPtr, out, 1);
    }
}

// round 5
// speedup vs baseline: 1.9370x; 1.1225x over previous
#include <cuda_runtime.h>
#include <cuda_bf16.h>
#include <math.h>
#include <stdint.h>

#define NNODES 50000
#define MPAD   50048      // 391 * 128
#define KD     256
#define HEADS  4
#define EMAX   1700000

// ---------------- device scratch --------------------------------------------
__device__ float          g_hs[MPAD * KD];      // source transform (fp32)
__device__ __nv_bfloat16  g_Ahi[MPAD * KD];     // activation split hi
__device__ __nv_bfloat16  g_Alo[MPAD * KD];     // activation split lo
__device__ __nv_bfloat16  g_Bthi[3 * KD * KD];  // W^T split hi, all layers
__device__ __nv_bfloat16  g_Btlo[3 * KD * KD];  // W^T split lo, all layers
__device__ float          g_as[MPAD * HEADS];
__device__ float          g_ad[NNODES * HEADS];
__device__ float          g_vd[3 * KD * HEADS]; // Wd_l @ att_d_l, [l][k][h]
__device__ int            g_deg[NNODES];
__device__ int            g_rowptr[NNODES + 1];
__device__ int            g_cursor[NNODES];
__device__ int            g_srcs[EMAX];         // CSR-ordered SOURCE ids

// ---------------- helpers ----------------------------------------------------
__device__ __forceinline__ void split_pair(float a, float b, unsigned& hi, unsigned& lo) {
    __nv_bfloat16 ha = __float2bfloat16(a), hb = __float2bfloat16(b);
    float ra = a - __bfloat162float(ha);
    float rb = b - __bfloat162float(hb);
    __nv_bfloat162 h2 = __halves2bfloat162(ha, hb);
    __nv_bfloat162 l2 = __floats2bfloat162_rn(ra, rb);
    hi = *reinterpret_cast<unsigned*>(&h2);
    lo = *reinterpret_cast<unsigned*>(&l2);
}

__device__ __forceinline__ void mma_bf16(float* c, const uint32_t* a, const uint32_t* b) {
    asm volatile(
        "mma.sync.aligned.m16n8k16.row.col.f32.bf16.bf16.f32 "
        "{%0,%1,%2,%3},{%4,%5,%6,%7},{%8,%9},{%0,%1,%2,%3};"
        : "+f"(c[0]), "+f"(c[1]), "+f"(c[2]), "+f"(c[3])
        : "r"(a[0]), "r"(a[1]), "r"(a[2]), "r"(a[3]), "r"(b[0]), "r"(b[1]));
}

#define CP_ASYNC16(dst_u32, src_ptr) \
    asm volatile("cp.async.cg.shared.global [%0], [%1], 16;" \
                 :: "r"(dst_u32), "l"(src_ptr))
#define CP_COMMIT() asm volatile("cp.async.commit_group;" ::: "memory")
#define CP_WAIT0()  asm volatile("cp.async.wait_group 0;" ::: "memory")

// ---------------- CSR build --------------------------------------------------
__global__ void clear_deg_kernel() {
    int i = blockIdx.x * blockDim.x + threadIdx.x;
    if (i < NNODES) g_deg[i] = 0;
}
__global__ void count_deg_kernel(const int* __restrict__ dst, int e2) {
    int e = blockIdx.x * blockDim.x + threadIdx.x;
    if (e < e2) atomicAdd(&g_deg[dst[e]], 1);
}
__global__ void scan_kernel() {
    __shared__ int s[1024];
    int t = threadIdx.x;
    const int per = (NNODES + 1023) / 1024;
    int start = t * per;
    int end = start + per; if (end > NNODES) end = NNODES;
    int sum = 0;
    for (int i = start; i < end; i++) sum += g_deg[i];
    s[t] = sum;
    __syncthreads();
    for (int off = 1; off < 1024; off <<= 1) {
        int v = (t >= off) ? s[t - off] : 0;
        __syncthreads();
        s[t] += v;
        __syncthreads();
    }
    int run = (t > 0) ? s[t - 1] : 0;
    for (int i = start; i < end; i++) {
        int d = g_deg[i];
        g_rowptr[i] = run;
        g_cursor[i] = run;
        run += d;
    }
    if (t == 0) g_rowptr[NNODES] = s[1023];
}
__global__ void scatter_kernel(const int* __restrict__ src,
                               const int* __restrict__ dst, int e2) {
    int e = blockIdx.x * blockDim.x + threadIdx.x;
    if (e < e2) {
        int pos = atomicAdd(&g_cursor[dst[e]], 1);
        g_srcs[pos] = src[e];        // store SOURCE id directly
    }
}

// ---------------- layer-0 pre-split: x -> bf16 hi/lo -------------------------
__global__ void split_x_kernel(const float* __restrict__ A, int nf4) {
    int i = blockIdx.x * blockDim.x + threadIdx.x;
    if (i >= nf4) return;
    float4 v = ((const float4*)A)[i];
    uint2 h, l;
    split_pair(v.x, v.y, h.x, l.x);
    split_pair(v.z, v.w, h.y, l.y);
    ((uint2*)g_Ahi)[i] = h;
    ((uint2*)g_Alo)[i] = l;
}

// ---------------- B transpose+split, all 3 layers ----------------------------
__global__ void btsplit_all_kernel(const float* __restrict__ W0,
                                   const float* __restrict__ W1,
                                   const float* __restrict__ W2) {
    int l = blockIdx.y;
    const float* W = (l == 0) ? W0 : (l == 1) ? W1 : W2;
    int i = blockIdx.x * blockDim.x + threadIdx.x;   // 65536 per layer
    int n = i >> 8, k = i & 255;
    float v = W[k * KD + n];
    __nv_bfloat16 h = __float2bfloat16(v);
    g_Bthi[l * KD * KD + i] = h;
    g_Btlo[l * KD * KD + i] = __float2bfloat16(v - __bfloat162float(h));
}

// ---------------- vd[l][k][h] = sum_c Wd_l[k, h*64+c] * ad_l[h*64+c] ---------
__global__ void compute_vd_kernel(const float* __restrict__ Wd,
                                  const float* __restrict__ ad, int loff) {
    int idx = threadIdx.x;             // 1024 threads
    int k = idx >> 2;
    int h = idx & 3;
    float s = 0.f;
#pragma unroll 8
    for (int c = 0; c < 64; c++) s += Wd[k * KD + h * 64 + c] * ad[h * 64 + c];
    g_vd[loff + k * 4 + h] = s;
}

// ---------------- layer-0 a_d = x . vd0  (warp per node) ---------------------
__global__ void __launch_bounds__(256) ad0_kernel(const float* __restrict__ X) {
    __shared__ float svd[KD * 4];
    int tid = threadIdx.x;
    for (int i = tid; i < KD * 4; i += 256) svd[i] = g_vd[i];
    __syncthreads();
    int warp = tid >> 5, lane = tid & 31;
    int n = blockIdx.x * 8 + warp;
    if (n >= NNODES) return;
    const float4* x4 = (const float4*)X + (long)n * 64;
    float a0 = 0.f, a1 = 0.f, a2 = 0.f, a3 = 0.f;
#pragma unroll
    for (int g4 = 0; g4 < 2; g4++) {
        float4 xv = x4[lane * 2 + g4];
        const float* p = &svd[(lane * 8 + g4 * 4) * 4];
        a0 += xv.x * p[0] + xv.y * p[4] + xv.z * p[8]  + xv.w * p[12];
        a1 += xv.x * p[1] + xv.y * p[5] + xv.z * p[9]  + xv.w * p[13];
        a2 += xv.x * p[2] + xv.y * p[6] + xv.z * p[10] + xv.w * p[14];
        a3 += xv.x * p[3] + xv.y * p[7] + xv.z * p[11] + xv.w * p[15];
    }
#pragma unroll
    for (int off = 16; off > 0; off >>= 1) {
        a0 += __shfl_xor_sync(0xffffffffu, a0, off);
        a1 += __shfl_xor_sync(0xffffffffu, a1, off);
        a2 += __shfl_xor_sync(0xffffffffu, a2, off);
        a3 += __shfl_xor_sync(0xffffffffu, a3, off);
    }
    if (lane == 0) ((float4*)g_ad)[n] = make_float4(a0, a1, a2, a3);
}

// ---------------- GEMM: g_hs = A @ W_l, cp.async 2-stage, fused a_s ----------
// grid (391, 2), 256 threads. CTA tile 128x128, BK=32.
// a_s: block-shared reduction, direct store (each (row,head) owned by 1 block).
#define S32 20
#define STAGE_W 10240        // words per stage: 4 arrays * 128*20
__global__ void __launch_bounds__(256) gemm_mma_kernel(const float* __restrict__ attS,
                                                       const __nv_bfloat16* __restrict__ Bh,
                                                       const __nv_bfloat16* __restrict__ Bl) {
    extern __shared__ uint32_t smem_u[];
    __shared__ float s_as[128][2];
    const int tid = threadIdx.x;
    const int wid = tid >> 5, lane = tid & 31;
    const int wm = wid >> 2, wn = wid & 3;
    const int row0 = blockIdx.x * 128;
    const int n0 = blockIdx.y * 128;
    const int g8 = lane >> 2, tq = lane & 3;
    const uint32_t smem_b = (uint32_t)__cvta_generic_to_shared(smem_u);

    ((float*)s_as)[tid] = 0.f;          // 256 threads cover 128*2

    const int lr0 = tid >> 2;
    const int lc4 = tid & 3;
    float c[4][4][4];
#pragma unroll
    for (int mt = 0; mt < 4; mt++)
#pragma unroll
        for (int nt = 0; nt < 4; nt++)
#pragma unroll
            for (int j = 0; j < 4; j++) c[mt][nt][j] = 0.f;

#define LOAD_CHUNK(stg, cc) do {                                               \
    int k0 = (cc) * 32;                                                        \
    _Pragma("unroll")                                                          \
    for (int i = 0; i < 2; i++) {                                              \
        int r = lr0 + i * 64;                                                  \
        long ga = (long)(row0 + r) * KD + k0 + lc4 * 8;                        \
        long gb = (long)(n0 + r) * KD + k0 + lc4 * 8;                          \
        uint32_t so = smem_b + ((stg) * STAGE_W + r * S32 + lc4 * 4) * 4;      \
        CP_ASYNC16(so,            g_Ahi + ga);                                 \
        CP_ASYNC16(so + 2560 * 4, g_Alo + ga);                                 \
        CP_ASYNC16(so + 5120 * 4, Bh + gb);                                    \
        CP_ASYNC16(so + 7680 * 4, Bl + gb);                                    \
    }                                                                          \
} while (0)

    LOAD_CHUNK(0, 0);
    CP_COMMIT();

    for (int cch = 0; cch < 8; cch++) {
        const int stg = cch & 1;
        CP_WAIT0();
        __syncthreads();
        if (cch < 7) { LOAD_CHUNK(stg ^ 1, cch + 1); CP_COMMIT(); }
        const uint32_t* sAh = smem_u + stg * STAGE_W;
        const uint32_t* sAl = sAh + 2560;
        const uint32_t* sBh = sAh + 5120;
        const uint32_t* sBl = sAh + 7680;
#pragma unroll
        for (int kk = 0; kk < 2; kk++) {
            const int kb = kk * 8;
            uint32_t ah[4][4], al[4][4], bh[4][2], bl[4][2];
#pragma unroll
            for (int mt = 0; mt < 4; mt++) {
                int r = (wm * 64 + mt * 16 + g8) * S32 + kb + tq;
                int r8 = r + 8 * S32;
                ah[mt][0] = sAh[r];     ah[mt][1] = sAh[r8];
                ah[mt][2] = sAh[r + 4]; ah[mt][3] = sAh[r8 + 4];
                al[mt][0] = sAl[r];     al[mt][1] = sAl[r8];
                al[mt][2] = sAl[r + 4]; al[mt][3] = sAl[r8 + 4];
            }
#pragma unroll
            for (int nt = 0; nt < 4; nt++) {
                int r = (wn * 32 + nt * 8 + g8) * S32 + kb + tq;
                bh[nt][0] = sBh[r]; bh[nt][1] = sBh[r + 4];
                bl[nt][0] = sBl[r]; bl[nt][1] = sBl[r + 4];
            }
#pragma unroll
            for (int mt = 0; mt < 4; mt++)
#pragma unroll
                for (int nt = 0; nt < 4; nt++) {
                    mma_bf16(c[mt][nt], ah[mt], bh[nt]);
                    mma_bf16(c[mt][nt], ah[mt], bl[nt]);
                    mma_bf16(c[mt][nt], al[mt], bh[nt]);
                }
        }
        __syncthreads();
    }

    // epilogue 1: fragments -> g_hs
#pragma unroll
    for (int mt = 0; mt < 4; mt++) {
        int r = row0 + wm * 64 + mt * 16 + g8;
#pragma unroll
        for (int nt = 0; nt < 4; nt++) {
            int col = n0 + wn * 32 + nt * 8 + tq * 2;
            *(float2*)&g_hs[(long)r * KD + col] = make_float2(c[mt][nt][0], c[mt][nt][1]);
            *(float2*)&g_hs[(long)(r + 8) * KD + col] = make_float2(c[mt][nt][2], c[mt][nt][3]);
        }
    }
    // epilogue 2: fused a_s via block-shared reduction (no global atomics)
    {
        float p0[4] = {0.f, 0.f, 0.f, 0.f};
        float p1[4] = {0.f, 0.f, 0.f, 0.f};
#pragma unroll
        for (int nt = 0; nt < 4; nt++) {
            int col = n0 + wn * 32 + nt * 8 + tq * 2;
            float a0 = attS[col], a1 = attS[col + 1];
#pragma unroll
            for (int mt = 0; mt < 4; mt++) {
                p0[mt] += c[mt][nt][0] * a0 + c[mt][nt][1] * a1;
                p1[mt] += c[mt][nt][2] * a0 + c[mt][nt][3] * a1;
            }
        }
        int hl = wn >> 1;
#pragma unroll
        for (int mt = 0; mt < 4; mt++) {
            p0[mt] += __shfl_xor_sync(0xffffffffu, p0[mt], 1);
            p0[mt] += __shfl_xor_sync(0xffffffffu, p0[mt], 2);
            p1[mt] += __shfl_xor_sync(0xffffffffu, p1[mt], 1);
            p1[mt] += __shfl_xor_sync(0xffffffffu, p1[mt], 2);
            if (tq == 0) {
                int rl = wm * 64 + mt * 16 + g8;
                atomicAdd(&s_as[rl][hl], p0[mt]);
                atomicAdd(&s_as[rl + 8][hl], p1[mt]);
            }
        }
        __syncthreads();
        int rl = tid >> 1, h2 = tid & 1;
        g_as[(row0 + rl) * 4 + blockIdx.y * 2 + h2] = s_as[rl][h2];
    }
}

// ---------------- aggregation: 128 thr/node, fused softmax denominator -------
// mode 0: elu(acc/den + bias) -> split to Ahi/Alo; a_d(next) via vdn
// mode 1: head-mean + b2 + log_softmax -> out[n,64]
__global__ void __launch_bounds__(128) aggregate_kernel(const float* __restrict__ bias,
                                                        const float* __restrict__ vdn,
                                                        float* __restrict__ out,
                                                        int mode) {
    __shared__ float2 stage[4][32];
    __shared__ float  s_adp[4][4];
    __shared__ float  sh[256];
    __shared__ float  s_red[2];

    const int n = blockIdx.x;
    const int tid = threadIdx.x;
    const int w = tid >> 5, lane = tid & 31;
    const int base = g_rowptr[n];
    const int deg = g_rowptr[n + 1] - base;

    const float adw = g_ad[n * 4 + w];
    const float2* __restrict__ hs2 = (const float2*)g_hs;
    const int colIdx = w * 32 + lane;

    float2 acc = make_float2(0.f, 0.f);
    float exsum = 0.f;
    for (int cs = 0; cs < deg; cs += 32) {
        int m = deg - cs; if (m > 32) m = 32;
        float ex = 0.f; int sI = 0;
        if (lane < m) {
            sI = g_srcs[base + cs + lane];
            float al = g_as[sI * 4 + w] + adw;
            al = al > 0.f ? al : 0.2f * al;
            ex = __expf(al);
            exsum += ex;
        }
        stage[w][lane] = make_float2(ex, __int_as_float(sI));
        __syncwarp();
#pragma unroll 4
        for (int j = 0; j < m; j++) {
            float2 st = stage[w][j];
            int s = __float_as_int(st.y);
            float2 hv = hs2[s * 128 + colIdx];
            acc.x += st.x * hv.x;
            acc.y += st.x * hv.y;
        }
        __syncwarp();
    }
    // denominator: warp-reduce of per-lane exp sums
#pragma unroll
    for (int off = 16; off > 0; off >>= 1)
        exsum += __shfl_xor_sync(0xffffffffu, exsum, off);
    const float den = exsum + 1e-16f;

    const int col0 = w * 64 + lane * 2;
    float v0 = acc.x / den;
    float v1 = acc.y / den;
    if (mode == 0) {
        v0 += bias[col0];
        v1 += bias[col0 + 1];
        v0 = v0 > 0.f ? v0 : expm1f(v0);
        v1 = v1 > 0.f ? v1 : expm1f(v1);
        unsigned hi, lo;
        split_pair(v0, v1, hi, lo);
        ((uint32_t*)g_Ahi)[n * 128 + colIdx] = hi;
        ((uint32_t*)g_Alo)[n * 128 + colIdx] = lo;
        // a_d for next layer
        const float* p0 = &vdn[col0 * 4];
        float q0 = v0 * p0[0] + v1 * p0[4];
        float q1 = v0 * p0[1] + v1 * p0[5];
        float q2 = v0 * p0[2] + v1 * p0[6];
        float q3 = v0 * p0[3] + v1 * p0[7];
#pragma unroll
        for (int off = 16; off > 0; off >>= 1) {
            q0 += __shfl_xor_sync(0xffffffffu, q0, off);
            q1 += __shfl_xor_sync(0xffffffffu, q1, off);
            q2 += __shfl_xor_sync(0xffffffffu, q2, off);
            q3 += __shfl_xor_sync(0xffffffffu, q3, off);
        }
        if (lane < 4) {
            float q = lane == 0 ? q0 : lane == 1 ? q1 : lane == 2 ? q2 : q3;
            s_adp[w][lane] = q;
        }
        __syncthreads();
        if (tid < 4)
            g_ad[n * 4 + tid] = s_adp[0][tid] + s_adp[1][tid] + s_adp[2][tid] + s_adp[3][tid];
    } else {
        sh[col0] = v0;
        sh[col0 + 1] = v1;
        __syncthreads();
        if (tid < 64)
            sh[tid] = 0.25f * (sh[tid] + sh[tid + 64] + sh[tid + 128] + sh[tid + 192]) + bias[tid];
        __syncthreads();
        if (tid < 32) {
            float a = fmaxf(sh[tid], sh[tid + 32]);
#pragma unroll
            for (int off = 16; off > 0; off >>= 1)
                a = fmaxf(a, __shfl_xor_sync(0xffffffffu, a, off));
            if (tid == 0) s_red[0] = a;
        }
        __syncthreads();
        if (tid < 32) {
            float mx = s_red[0];
            float a = expf(sh[tid] - mx) + expf(sh[tid + 32] - mx);
#pragma unroll
            for (int off = 16; off > 0; off >>= 1)
                a += __shfl_xor_sync(0xffffffffu, a, off);
            if (tid == 0) s_red[1] = a;
        }
        __syncthreads();
        if (tid < 64) out[(long)n * 64 + tid] = sh[tid] - s_red[0] - logf(s_red[1]);
    }
}

// ---------------- launch -----------------------------------------------------
extern "C" void kernel_launch(void* const* d_in, const int* in_sizes, int n_in,
                              void* d_out, int out_size) {
    const float* x = (const float*)d_in[0];
    const int* ei = (const int*)d_in[1];
    int e2 = in_sizes[1] / 2;
    const int* src = ei;
    const int* dstp = ei + e2;
    const float* Ws[3] = {(const float*)d_in[2], (const float*)d_in[7],  (const float*)d_in[12]};
    const float* Wd[3] = {(const float*)d_in[3], (const float*)d_in[8],  (const float*)d_in[13]};
    const float* As[3] = {(const float*)d_in[4], (const float*)d_in[9],  (const float*)d_in[14]};
    const float* Ad[3] = {(const float*)d_in[5], (const float*)d_in[10], (const float*)d_in[15]};
    const float* Bb[3] = {(const float*)d_in[6], (const float*)d_in[11], (const float*)d_in[16]};
    float* out = (float*)d_out;

    float* vdPtr = 0;              cudaGetSymbolAddress((void**)&vdPtr, g_vd);
    __nv_bfloat16* bthiPtr = 0;    cudaGetSymbolAddress((void**)&bthiPtr, g_Bthi);
    __nv_bfloat16* btloPtr = 0;    cudaGetSymbolAddress((void**)&btloPtr, g_Btlo);

    const int GEMM_SMEM = 2 * STAGE_W * 4;   // 81920 B
    cudaFuncSetAttribute(gemm_mma_kernel, cudaFuncAttributeMaxDynamicSharedMemorySize,
                         GEMM_SMEM);

    int gE = (e2 + 255) / 256;

    // CSR by destination (stores src ids in CSR order)
    clear_deg_kernel<<<(NNODES + 255) / 256, 256>>>();
    count_deg_kernel<<<gE, 256>>>(dstp, e2);
    scan_kernel<<<1, 1024>>>();
    scatter_kernel<<<gE, 256>>>(src, dstp, e2);

    // one-time: x split, all weights split, all vd, layer-0 a_d
    split_x_kernel<<<(NNODES * KD / 4 + 255) / 256, 256>>>(x, NNODES * KD / 4);
    btsplit_all_kernel<<<dim3(KD * KD / 256, 3), 256>>>(Ws[0], Ws[1], Ws[2]);
    for (int l = 0; l < 3; l++)
        compute_vd_kernel<<<1, 1024>>>(Wd[l], Ad[l], l * KD * HEADS);
    ad0_kernel<<<(NNODES + 7) / 8, 256>>>(x);

    for (int l = 0; l < 3; l++) {
        gemm_mma_kernel<<<dim3(MPAD / 128, 2), 256, GEMM_SMEM>>>(
            As[l], bthiPtr + (size_t)l * KD * KD, btloPtr + (size_t)l * KD * KD);
        if (l < 2)
            aggregate_kernel<<<NNODES, 128>>>(Bb[l], vdPtr + (l + 1) * KD * HEADS,
                                              (float*)0, 0);
        else
            aggregate_kernel<<<NNODES, 128>>>(Bb[l], vdPtr, out, 1);
    }
}